// round 1
// baseline (speedup 1.0000x reference)
#include <cuda_runtime.h>
#include <math.h>

// ---------------- problem constants ----------------
#define BSZ   64
#define HW    1024        // 32*32
#define CH    684
#define HIDD  256
#define NPP   512
#define KCONV 121         // 11*11
#define KTOT  805         // 684 + 121
#define KPAD  816         // 51 * 16
#define PADW  42          // 32 + 2*5

// ---------------- device scratch (no cudaMalloc allowed) ----------------
__device__ float g_Bmat[KTOT * NPP];      // [k][p] combined B: Ua^T rows + folded Uf*convQ rows
__device__ float g_convQT[KCONV * 256];   // [t][q]
__device__ float g_betaPad[BSZ * PADW * PADW];
__device__ float g_embT[HIDD * BSZ];      // [k][b]
__device__ float g_hidT[HIDD * BSZ];      // [k][b]
__device__ float g_predT[HIDD * BSZ];     // [j][b]
__device__ float g_query[BSZ * NPP];      // [b][p], includes all biases
__device__ float g_D[NPP];                // Ua_b + Uf_b + Uf*convQ_b
__device__ float g_et[4 * BSZ * HW];      // 4 N-block partial slices (deterministic, no atomics)
__device__ float g_ctxT[CH * BSZ];        // [c][b]
__device__ float g_h2T[HIDD * BSZ];       // [j][b]
__device__ float g_oT[HIDD * BSZ];        // [i][b]

// ---------------- K0a: transpose convQ weights ----------------
__global__ void k_convT(const float* __restrict__ convQ_w) {
    int idx = blockIdx.x * 256 + threadIdx.x;       // idx = t*256 + q
    if (idx >= KCONV * 256) return;
    int q = idx & 255;
    int t = idx >> 8;
    g_convQT[idx] = convQ_w[q * KCONV + t];
}

// ---------------- K0b: fold Uf_w @ convQ_w into Bmat rows [684..805) ----------------
__global__ void k_foldUf(const float* __restrict__ Uf_w) {
    int w = (blockIdx.x * 256 + threadIdx.x) >> 5;  // global warp id
    int lane = threadIdx.x & 31;
    if (w >= NPP * KCONV) return;
    int t = w % KCONV;
    int p = w / KCONV;
    float acc = 0.f;
    for (int q = lane; q < 256; q += 32)
        acc += Uf_w[p * 256 + q] * g_convQT[t * 256 + q];
    #pragma unroll
    for (int o = 16; o; o >>= 1) acc += __shfl_down_sync(0xffffffffu, acc, o);
    if (lane == 0) g_Bmat[(CH + t) * NPP + p] = acc;
}

// ---------------- K0c: transpose Ua_w into Bmat rows [0..684) ----------------
__global__ void k_transUa(const float* __restrict__ Ua_w) {
    int idx = blockIdx.x * 256 + threadIdx.x;       // idx = c*512 + p
    if (idx >= CH * NPP) return;
    int p = idx & (NPP - 1);
    int c = idx >> 9;
    g_Bmat[idx] = Ua_w[p * CH + c];
}

// ---------------- K0d: small preps: embT gather, hidT, D vector, padded beta ----------------
__global__ void k_misc(const int* __restrict__ x,
                       const float* __restrict__ hidden,
                       const float* __restrict__ emb,
                       const float* __restrict__ alpha,
                       const float* __restrict__ Uf_w,
                       const float* __restrict__ convQ_b,
                       const float* __restrict__ Ua_b,
                       const float* __restrict__ Uf_b) {
    int idx = blockIdx.x * 256 + threadIdx.x;
    if (idx < 16384) {                               // embT[k*64+b] = emb[x[b]][k]
        int k = idx >> 6, b = idx & 63;
        g_embT[idx] = emb[x[b] * 256 + k];
    } else if (idx < 32768) {                        // hidT
        int i = idx - 16384;
        int k = i >> 6, b = i & 63;
        g_hidT[i] = hidden[b * 256 + k];
    } else if (idx < 33280) {                        // D[p]
        int p = idx - 32768;
        float acc = Ua_b[p] + Uf_b[p];
        for (int q = 0; q < 256; q++) acc += Uf_w[p * 256 + q] * convQ_b[q];
        g_D[p] = acc;
    } else if (idx < 33280 + BSZ * PADW * PADW) {    // betaPad
        int i = idx - 33280;
        int b = i / (PADW * PADW);
        int pos = i % (PADW * PADW);
        int py = pos / PADW, px = pos % PADW;
        int y = py - 5, xx = px - 5;
        float v = 0.f;
        if (y >= 0 && y < 32 && xx >= 0 && xx < 32) v = alpha[b * HW + y * 32 + xx];
        g_betaPad[i] = v;
    }
}

// ---------------- K1: embed + GRU1 -> predT ----------------
__global__ void k_gru1(const float* __restrict__ wih, const float* __restrict__ whh,
                       const float* __restrict__ bih, const float* __restrict__ bhh) {
    int b = threadIdx.x;
    int j = blockIdx.x * 8 + threadIdx.y;
    float gi0 = bih[j], gi1 = bih[256 + j], gi2 = bih[512 + j];
    float gh0 = bhh[j], gh1 = bhh[256 + j], gh2 = bhh[512 + j];
    for (int k = 0; k < 256; k++) {
        float e = g_embT[k * 64 + b];
        float h = g_hidT[k * 64 + b];
        gi0 += e * wih[j * 256 + k];
        gi1 += e * wih[(256 + j) * 256 + k];
        gi2 += e * wih[(512 + j) * 256 + k];
        gh0 += h * whh[j * 256 + k];
        gh1 += h * whh[(256 + j) * 256 + k];
        gh2 += h * whh[(512 + j) * 256 + k];
    }
    float r = 1.f / (1.f + expf(-(gi0 + gh0)));
    float z = 1.f / (1.f + expf(-(gi1 + gh1)));
    float n = tanhf(gi2 + r * gh2);
    float hprev = g_hidT[j * 64 + b];
    g_predT[j * 64 + b] = (1.f - z) * n + z * hprev;
}

// ---------------- K2: query[b][p] = pred @ Wa^T + Wa_b + D ----------------
__global__ void k_query(const float* __restrict__ Wa_w, const float* __restrict__ Wa_b) {
    int b = threadIdx.x;
    int p = blockIdx.x * 8 + threadIdx.y;
    float acc = Wa_b[p] + g_D[p];
    for (int j = 0; j < 256; j++)
        acc += g_predT[j * 64 + b] * Wa_w[p * 256 + j];
    g_query[b * NPP + p] = acc;
}

// ---------------- K3: fused attention GEMM ----------------
// A[m][k]: k<684 -> feature[b][k][l]; k in [684,805) -> im2col(betaPad)
// C = A @ Bmat ; epilogue: e_partial[m] += sum_p tanh(C + query)*Va[p]
#define BM 128
#define BN 128
#define BK 16
__global__ void __launch_bounds__(256) k_gemm(const float* __restrict__ feature,
                                              const float* __restrict__ Va_w) {
    __shared__ float As[BK][BM];
    __shared__ float Bs[BK][BN];
    __shared__ float red[BM][16];

    int n0 = blockIdx.x * BN;
    int m0 = blockIdx.y * BM;
    int b  = m0 >> 10;                    // 128-row tile never crosses a batch boundary
    int tid = threadIdx.x;
    int tx = tid & 15, ty = tid >> 4;

    float acc[8][8];
    #pragma unroll
    for (int r = 0; r < 8; r++)
        #pragma unroll
        for (int s = 0; s < 8; s++) acc[r][s] = 0.f;

    for (int k0 = 0; k0 < KPAD; k0 += BK) {
        #pragma unroll
        for (int i = 0; i < 8; i++) {
            int idx = tid + i * 256;
            int ak = idx >> 7, am = idx & 127;
            int k = k0 + ak;
            int m = m0 + am;
            int l = m & 1023;
            float v = 0.f;
            if (k < CH) {
                v = feature[(b * CH + k) * HW + l];
            } else if (k < KTOT) {
                int t = k - CH;
                int dy = t / 11, dx = t - dy * 11;
                int y = l >> 5, xx = l & 31;
                v = g_betaPad[b * (PADW * PADW) + (y + dy) * PADW + (xx + dx)];
            }
            As[ak][am] = v;
        }
        #pragma unroll
        for (int i = 0; i < 8; i++) {
            int idx = tid + i * 256;
            int bk = idx >> 7, bn = idx & 127;
            int k = k0 + bk;
            Bs[bk][bn] = (k < KTOT) ? g_Bmat[k * NPP + n0 + bn] : 0.f;
        }
        __syncthreads();
        #pragma unroll
        for (int kk = 0; kk < BK; kk++) {
            float a[8], bv[8];
            #pragma unroll
            for (int r = 0; r < 8; r++) a[r] = As[kk][ty * 8 + r];
            #pragma unroll
            for (int s = 0; s < 8; s++) bv[s] = Bs[kk][tx * 8 + s];
            #pragma unroll
            for (int r = 0; r < 8; r++)
                #pragma unroll
                for (int s = 0; s < 8; s++) acc[r][s] += a[r] * bv[s];
        }
        __syncthreads();
    }

    // epilogue: tanh(C + query) * Va, reduce over the 128 p-columns of this block
    float rowsum[8];
    #pragma unroll
    for (int r = 0; r < 8; r++) rowsum[r] = 0.f;
    #pragma unroll
    for (int s = 0; s < 8; s++) {
        int p = n0 + tx * 8 + s;
        float qv = g_query[b * NPP + p];
        float va = Va_w[p];
        #pragma unroll
        for (int r = 0; r < 8; r++)
            rowsum[r] += tanhf(acc[r][s] + qv) * va;
    }
    #pragma unroll
    for (int r = 0; r < 8; r++) red[ty * 8 + r][tx] = rowsum[r];
    __syncthreads();
    if (tid < 128) {
        float s = 0.f;
        #pragma unroll
        for (int j = 0; j < 16; j++) s += red[tid][j];
        g_et[blockIdx.x * (BSZ * HW) + m0 + tid] = s;   // per-N-block slice: deterministic
    }
}

// ---------------- K4: softmax over HW per batch ----------------
__global__ void k_softmax(const float* __restrict__ Va_b, float* __restrict__ out_alpha) {
    __shared__ float sx[HW];
    __shared__ float sred[256];
    int b = blockIdx.x;
    int tid = threadIdx.x;
    float vab = Va_b[0];
    float ps = 0.f;
    for (int i = tid; i < HW; i += 256) {
        int m = b * HW + i;
        float e = g_et[m] + g_et[65536 + m] + g_et[131072 + m] + g_et[196608 + m] + vab;
        float ex = expf(e);
        sx[i] = ex;
        ps += ex;
    }
    sred[tid] = ps;
    __syncthreads();
    for (int o = 128; o; o >>= 1) {
        if (tid < o) sred[tid] += sred[tid + o];
        __syncthreads();
    }
    float denom = sred[0] + 1e-8f;
    for (int i = tid; i < HW; i += 256)
        out_alpha[b * HW + i] = sx[i] / denom;
}

// ---------------- K5: context[b][c] = feature[b][c][:] . alpha[b][:] ----------------
__global__ void k_context(const float* __restrict__ feature, const float* __restrict__ alpha) {
    __shared__ float sa[HW];
    int b = blockIdx.y;
    int tid = threadIdx.x;
    for (int i = tid; i < HW; i += 256) sa[i] = alpha[b * HW + i];
    __syncthreads();
    int warp = tid >> 5, lane = tid & 31;
    int c = blockIdx.x * 8 + warp;
    if (c < CH) {
        const float* fr = feature + (b * CH + c) * HW;
        float acc = 0.f;
        for (int i = lane; i < HW; i += 32) acc += fr[i] * sa[i];
        #pragma unroll
        for (int o = 16; o; o >>= 1) acc += __shfl_down_sync(0xffffffffu, acc, o);
        if (lane == 0) g_ctxT[c * 64 + b] = acc;
    }
}

// ---------------- K6: GRU2 -> h2 (also writes output h2) ----------------
__global__ void k_gru2(const float* __restrict__ wih, const float* __restrict__ whh,
                       const float* __restrict__ bih, const float* __restrict__ bhh,
                       float* __restrict__ out_h2) {
    int b = threadIdx.x;
    int j = blockIdx.x * 8 + threadIdx.y;
    float gi0 = bih[j], gi1 = bih[256 + j], gi2 = bih[512 + j];
    float gh0 = bhh[j], gh1 = bhh[256 + j], gh2 = bhh[512 + j];
    for (int c = 0; c < CH; c++) {
        float cv = g_ctxT[c * 64 + b];
        gi0 += cv * wih[j * CH + c];
        gi1 += cv * wih[(256 + j) * CH + c];
        gi2 += cv * wih[(512 + j) * CH + c];
    }
    for (int k = 0; k < 256; k++) {
        float h = g_predT[k * 64 + b];
        gh0 += h * whh[j * 256 + k];
        gh1 += h * whh[(256 + j) * 256 + k];
        gh2 += h * whh[(512 + j) * 256 + k];
    }
    float r = 1.f / (1.f + expf(-(gi0 + gh0)));
    float z = 1.f / (1.f + expf(-(gi1 + gh1)));
    float n = tanhf(gi2 + r * gh2);
    float hprev = g_predT[j * 64 + b];
    float h2 = (1.f - z) * n + z * hprev;
    out_h2[b * 256 + j] = h2;
    g_h2T[j * 64 + b] = h2;
}

// ---------------- K7: o = embedded + Ws h2 + Wc context ----------------
__global__ void k_ocomp(const float* __restrict__ Ws_w, const float* __restrict__ Ws_b,
                        const float* __restrict__ Wc_w, const float* __restrict__ Wc_b) {
    int b = threadIdx.x;
    int i = blockIdx.x * 8 + threadIdx.y;
    float acc = g_embT[i * 64 + b] + Ws_b[i] + Wc_b[i];
    for (int j = 0; j < 256; j++)
        acc += g_h2T[j * 64 + b] * Ws_w[i * 256 + j];
    for (int c = 0; c < CH; c++)
        acc += g_ctxT[c * 64 + b] * Wc_w[i * CH + c];
    g_oT[i * 64 + b] = acc;
}

// ---------------- K8: maxout pairs + final projection ----------------
__global__ void k_logits(const float* __restrict__ Wo_w, const float* __restrict__ Wo_b,
                         float* __restrict__ out_logits) {
    int b = threadIdx.x;
    int v = blockIdx.x * 8 + threadIdx.y;
    float acc = Wo_b[v];
    for (int i2 = 0; i2 < 128; i2++) {
        float m = fmaxf(g_oT[(2 * i2) * 64 + b], g_oT[(2 * i2 + 1) * 64 + b]);
        acc += m * Wo_w[v * 128 + i2];
    }
    out_logits[b * 128 + v] = acc;
}

// ---------------- launch ----------------
extern "C" void kernel_launch(void* const* d_in, const int* in_sizes, int n_in,
                              void* d_out, int out_size) {
    (void)in_sizes; (void)n_in; (void)out_size;
    const int*   x        = (const int*)  d_in[0];
    const float* hidden   = (const float*)d_in[1];
    const float* feature  = (const float*)d_in[2];
    const float* alpha    = (const float*)d_in[3];
    const float* emb      = (const float*)d_in[4];
    const float* gru1_wih = (const float*)d_in[5];
    const float* gru1_whh = (const float*)d_in[6];
    const float* gru1_bih = (const float*)d_in[7];
    const float* gru1_bhh = (const float*)d_in[8];
    const float* gru2_wih = (const float*)d_in[9];
    const float* gru2_whh = (const float*)d_in[10];
    const float* gru2_bih = (const float*)d_in[11];
    const float* gru2_bhh = (const float*)d_in[12];
    const float* convQ_w  = (const float*)d_in[13];
    const float* convQ_b  = (const float*)d_in[14];
    const float* Wa_w     = (const float*)d_in[15];
    const float* Wa_b     = (const float*)d_in[16];
    const float* Ua_w     = (const float*)d_in[17];
    const float* Ua_b     = (const float*)d_in[18];
    const float* Uf_w     = (const float*)d_in[19];
    const float* Uf_b     = (const float*)d_in[20];
    const float* Va_w     = (const float*)d_in[21];
    const float* Va_b     = (const float*)d_in[22];
    const float* Ws_w     = (const float*)d_in[23];
    const float* Ws_b     = (const float*)d_in[24];
    const float* Wc_w     = (const float*)d_in[25];
    const float* Wc_b     = (const float*)d_in[26];
    const float* Wo_w     = (const float*)d_in[27];
    const float* Wo_b     = (const float*)d_in[28];

    float* out_logits = (float*)d_out;                    // 64*128
    float* out_h2     = out_logits + 64 * 128;            // 64*256
    float* out_alpha  = out_h2 + 64 * 256;                // 64*1024

    k_convT  <<<KCONV, 256>>>(convQ_w);
    k_foldUf <<<(NPP * KCONV + 7) / 8, 256>>>(Uf_w);
    k_transUa<<<(CH * NPP + 255) / 256, 256>>>(Ua_w);
    k_misc   <<<(33280 + BSZ * PADW * PADW + 255) / 256, 256>>>(
                 x, hidden, emb, alpha, Uf_w, convQ_b, Ua_b, Uf_b);
    k_gru1   <<<32, dim3(64, 8)>>>(gru1_wih, gru1_whh, gru1_bih, gru1_bhh);
    k_query  <<<64, dim3(64, 8)>>>(Wa_w, Wa_b);
    k_gemm   <<<dim3(4, 512), 256>>>(feature, Va_w);
    k_softmax<<<64, 256>>>(Va_b, out_alpha);
    k_context<<<dim3((CH + 7) / 8, 64), 256>>>(feature, out_alpha);
    k_gru2   <<<32, dim3(64, 8)>>>(gru2_wih, gru2_whh, gru2_bih, gru2_bhh, out_h2);
    k_ocomp  <<<32, dim3(64, 8)>>>(Ws_w, Ws_b, Wc_w, Wc_b);
    k_logits <<<16, dim3(64, 8)>>>(Wo_w, Wo_b, out_logits);
}

// round 3
// speedup vs baseline: 3.3604x; 3.3604x over previous
#include <cuda_runtime.h>
#include <math.h>
#include <stdint.h>

// ---------------- problem constants ----------------
#define BSZ   64
#define HW    1024        // 32*32
#define CH    684
#define HIDD  256
#define NPP   512
#define KCONV 121         // 11*11
#define KTOT  805         // 684 + 121
#define KPAD  832         // 52 * 16
#define NCHUNK 52         // K chunks of 16
#define PADW  42          // 32 + 2*5

// ---------------- device scratch (no cudaMalloc allowed) ----------------
__device__ float g_BmatT[KPAD * NPP];     // [k][p] combined B (tf32-rounded): Ua^T + folded Uf*convQ
__device__ float g_convQT[KCONV * 256];   // [t][q]
__device__ float g_betaPad[BSZ * PADW * PADW];
__device__ float g_embT[HIDD * BSZ];      // [k][b]
__device__ float g_hidT[HIDD * BSZ];      // [k][b]
__device__ float g_predT[HIDD * BSZ];     // [j][b]
__device__ float g_query[BSZ * NPP];      // [b][p], includes Wa_b + D
__device__ float g_D[NPP];                // Ua_b + Uf_b + Uf*convQ_b
__device__ float g_et[4 * BSZ * HW];      // 4 N-block partial slices (deterministic)
__device__ float g_ctxT[CH * BSZ];        // [c][b]
__device__ float g_h2T[HIDD * BSZ];       // [j][b]
__device__ float g_oT[HIDD * BSZ];        // [i][b]

__device__ __forceinline__ float to_tf32(float x) {
    float y; asm("cvt.rna.tf32.f32 %0, %1;" : "=f"(y) : "f"(x)); return y;
}

// ---------------- K0a: transpose convQ weights ----------------
__global__ void k_convT(const float* __restrict__ convQ_w) {
    int idx = blockIdx.x * 256 + threadIdx.x;       // idx = t*256 + q
    if (idx >= KCONV * 256) return;
    int q = idx & 255;
    int t = idx >> 8;
    g_convQT[idx] = convQ_w[q * KCONV + t];
}

// ---------------- K0b: fold Uf_w @ convQ_w into BmatT rows [684..805) ----------------
__global__ void k_foldUf(const float* __restrict__ Uf_w) {
    int w = (blockIdx.x * 256 + threadIdx.x) >> 5;  // global warp id
    int lane = threadIdx.x & 31;
    if (w >= NPP * KCONV) return;
    int t = w % KCONV;
    int p = w / KCONV;
    float acc = 0.f;
    for (int q = lane; q < 256; q += 32)
        acc += Uf_w[p * 256 + q] * g_convQT[t * 256 + q];
    #pragma unroll
    for (int o = 16; o; o >>= 1) acc += __shfl_down_sync(0xffffffffu, acc, o);
    if (lane == 0) g_BmatT[(CH + t) * NPP + p] = to_tf32(acc);
}

// ---------------- K0c: Ua_w -> BmatT rows [0..684), zero tail ----------------
__global__ void k_bmatT(const float* __restrict__ Ua_w) {
    int idx = blockIdx.x * 256 + threadIdx.x;   // k*512 + p
    if (idx >= KPAD * NPP) return;
    int k = idx >> 9;
    int p = idx & 511;
    if (k < CH)        g_BmatT[idx] = to_tf32(Ua_w[p * CH + k]);
    else if (k >= KTOT) g_BmatT[idx] = 0.f;
}

// ---------------- K0d: embT, hidT, D vector (warp-reduce), padded beta ----------------
__global__ void k_misc(const int* __restrict__ x,
                       const float* __restrict__ hidden,
                       const float* __restrict__ emb,
                       const float* __restrict__ alpha,
                       const float* __restrict__ Uf_w,
                       const float* __restrict__ convQ_b,
                       const float* __restrict__ Ua_b,
                       const float* __restrict__ Uf_b) {
    int idx = blockIdx.x * 256 + threadIdx.x;
    if (idx < 16384) {                               // embT[k*64+b] = emb[x[b]][k]
        int k = idx >> 6, b = idx & 63;
        g_embT[idx] = emb[x[b] * 256 + k];
    } else if (idx < 32768) {                        // hidT
        int i = idx - 16384;
        g_hidT[i] = hidden[(i & 63) * 256 + (i >> 6)];
    } else if (idx < 49152) {                        // D[p], one warp per p
        int i = idx - 32768;
        int p = i >> 5, lane = i & 31;
        float acc = 0.f;
        for (int q = lane; q < 256; q += 32)
            acc += Uf_w[p * 256 + q] * convQ_b[q];
        #pragma unroll
        for (int o = 16; o; o >>= 1) acc += __shfl_down_sync(0xffffffffu, acc, o);
        if (lane == 0) g_D[p] = acc + Ua_b[p] + Uf_b[p];
    } else if (idx < 49152 + BSZ * PADW * PADW) {    // betaPad
        int i = idx - 49152;
        int b = i / (PADW * PADW);
        int pos = i % (PADW * PADW);
        int py = pos / PADW, px = pos % PADW;
        int y = py - 5, xx = px - 5;
        float v = 0.f;
        if (y >= 0 && y < 32 && xx >= 0 && xx < 32) v = alpha[b * HW + y * 32 + xx];
        g_betaPad[i] = v;
    }
}

// ---------------- K1: embed + GRU1 -> predT ----------------
__global__ void k_gru1(const float* __restrict__ wih, const float* __restrict__ whh,
                       const float* __restrict__ bih, const float* __restrict__ bhh) {
    int b = threadIdx.x;
    int j = blockIdx.x * 8 + threadIdx.y;
    float gi0 = bih[j], gi1 = bih[256 + j], gi2 = bih[512 + j];
    float gh0 = bhh[j], gh1 = bhh[256 + j], gh2 = bhh[512 + j];
    for (int k = 0; k < 256; k++) {
        float e = g_embT[k * 64 + b];
        float h = g_hidT[k * 64 + b];
        gi0 += e * wih[j * 256 + k];
        gi1 += e * wih[(256 + j) * 256 + k];
        gi2 += e * wih[(512 + j) * 256 + k];
        gh0 += h * whh[j * 256 + k];
        gh1 += h * whh[(256 + j) * 256 + k];
        gh2 += h * whh[(512 + j) * 256 + k];
    }
    float r = 1.f / (1.f + expf(-(gi0 + gh0)));
    float z = 1.f / (1.f + expf(-(gi1 + gh1)));
    float n = tanhf(gi2 + r * gh2);
    float hprev = g_hidT[j * 64 + b];
    g_predT[j * 64 + b] = (1.f - z) * n + z * hprev;
}

// ---------------- K2: query[b][p] = pred @ Wa^T + Wa_b + D ----------------
__global__ void k_query(const float* __restrict__ Wa_w, const float* __restrict__ Wa_b) {
    int b = threadIdx.x;
    int p = blockIdx.x * 8 + threadIdx.y;
    float acc = Wa_b[p] + g_D[p];
    for (int j = 0; j < 256; j++)
        acc += g_predT[j * 64 + b] * Wa_w[p * 256 + j];
    g_query[b * NPP + p] = acc;
}

// ---------------- K3: fused attention GEMM via mma.sync tf32 ----------------
// grid (4 nblk, 512 mblk), 256 threads = 8 warps (2 m x 4 n), warp tile 64x32.
// A[m][k]: feature + im2col(betaPad); B[k][p] = g_BmatT. BK=16 double buffered.
#define ASTRIDE 136
__global__ void __launch_bounds__(256) k_gemm_tc(const float* __restrict__ feature,
                                                 const float* __restrict__ Va_w) {
    __shared__ float As[2][16][ASTRIDE];
    __shared__ float Bs[2][16][ASTRIDE];
    __shared__ float s_red[128][5];

    int tid = threadIdx.x;
    int wid = tid >> 5, lane = tid & 31;
    int grp = lane >> 2, tig = lane & 3;
    int warp_m = wid >> 2, warp_n = wid & 3;     // 2 x 4

    int n0 = blockIdx.x * 128;
    int m0 = blockIdx.y * 128;
    int b  = m0 >> 10;
    int l0 = m0 & 1023;

    float c[4][4][4];
    #pragma unroll
    for (int mi = 0; mi < 4; mi++)
        #pragma unroll
        for (int ni = 0; ni < 4; ni++)
            #pragma unroll
            for (int j = 0; j < 4; j++) c[mi][ni][j] = 0.f;

    // staging regs
    float4 ta[2], tb[2];
    int kk_[2], m4_[2];
    #pragma unroll
    for (int i = 0; i < 2; i++) {
        int idx = i * 256 + tid;
        kk_[i] = idx >> 5;          // 0..15
        m4_[i] = (idx & 31) * 4;    // 0..124
    }

    #define LOAD_STAGE(c_)                                                            \
    {                                                                                 \
        int k0 = (c_) * 16;                                                           \
        _Pragma("unroll")                                                             \
        for (int i = 0; i < 2; i++) {                                                 \
            int kg = k0 + kk_[i];                                                     \
            if (kg < CH) {                                                            \
                ta[i] = *(const float4*)&feature[(b * CH + kg) * HW + l0 + m4_[i]];   \
            } else if (kg < KTOT) {                                                   \
                int t = kg - CH; int dy = t / 11, dx = t - dy * 11;                   \
                float tmp[4];                                                         \
                _Pragma("unroll")                                                     \
                for (int j = 0; j < 4; j++) {                                         \
                    int l = l0 + m4_[i] + j; int y = l >> 5, xx = l & 31;             \
                    tmp[j] = g_betaPad[b * (PADW * PADW) + (y + dy) * PADW + (xx + dx)]; \
                }                                                                     \
                ta[i] = make_float4(tmp[0], tmp[1], tmp[2], tmp[3]);                  \
            } else {                                                                  \
                ta[i] = make_float4(0.f, 0.f, 0.f, 0.f);                              \
            }                                                                         \
            tb[i] = *(const float4*)&g_BmatT[(k0 + kk_[i]) * NPP + n0 + m4_[i]];      \
        }                                                                             \
    }

    #define STORE_STAGE(s_)                                                           \
    {                                                                                 \
        _Pragma("unroll")                                                             \
        for (int i = 0; i < 2; i++) {                                                 \
            float* ap = &As[s_][kk_[i]][m4_[i]];                                      \
            ap[0] = to_tf32(ta[i].x); ap[1] = to_tf32(ta[i].y);                       \
            ap[2] = to_tf32(ta[i].z); ap[3] = to_tf32(ta[i].w);                       \
            *(float4*)&Bs[s_][kk_[i]][m4_[i]] = tb[i];                                \
        }                                                                             \
    }

    LOAD_STAGE(0);
    STORE_STAGE(0);
    __syncthreads();

    for (int cc = 0; cc < NCHUNK; cc++) {
        int s = cc & 1;
        if (cc + 1 < NCHUNK) LOAD_STAGE(cc + 1);

        #pragma unroll
        for (int ks = 0; ks < 2; ks++) {
            int kb = ks * 8;
            uint32_t af[4][4], bf[4][2];
            #pragma unroll
            for (int mi = 0; mi < 4; mi++) {
                int mr = warp_m * 64 + mi * 16 + grp;
                af[mi][0] = __float_as_uint(As[s][kb + tig][mr]);
                af[mi][1] = __float_as_uint(As[s][kb + tig][mr + 8]);
                af[mi][2] = __float_as_uint(As[s][kb + tig + 4][mr]);
                af[mi][3] = __float_as_uint(As[s][kb + tig + 4][mr + 8]);
            }
            #pragma unroll
            for (int ni = 0; ni < 4; ni++) {
                int nc = warp_n * 32 + ni * 8 + grp;
                bf[ni][0] = __float_as_uint(Bs[s][kb + tig][nc]);
                bf[ni][1] = __float_as_uint(Bs[s][kb + tig + 4][nc]);
            }
            #pragma unroll
            for (int mi = 0; mi < 4; mi++)
                #pragma unroll
                for (int ni = 0; ni < 4; ni++) {
                    asm("mma.sync.aligned.m16n8k8.row.col.f32.tf32.tf32.f32 "
                        "{%0,%1,%2,%3}, {%4,%5,%6,%7}, {%8,%9}, {%0,%1,%2,%3};"
                        : "+f"(c[mi][ni][0]), "+f"(c[mi][ni][1]),
                          "+f"(c[mi][ni][2]), "+f"(c[mi][ni][3])
                        : "r"(af[mi][0]), "r"(af[mi][1]), "r"(af[mi][2]), "r"(af[mi][3]),
                          "r"(bf[ni][0]), "r"(bf[ni][1]));
                }
        }

        if (cc + 1 < NCHUNK) {
            STORE_STAGE(1 - s);
            __syncthreads();
        }
    }

    // ---- epilogue: e[m] = sum_p tanh(C + query[b][p]) * Va[p] ----
    const float* qrow = g_query + b * NPP;
    #pragma unroll
    for (int mi = 0; mi < 4; mi++) {
        float rs0 = 0.f, rs1 = 0.f;
        #pragma unroll
        for (int ni = 0; ni < 4; ni++) {
            int ng = n0 + warp_n * 32 + ni * 8 + 2 * tig;
            float q0 = qrow[ng],     va0 = Va_w[ng];
            float q1 = qrow[ng + 1], va1 = Va_w[ng + 1];
            rs0 += tanhf(c[mi][ni][0] + q0) * va0 + tanhf(c[mi][ni][1] + q1) * va1;
            rs1 += tanhf(c[mi][ni][2] + q0) * va0 + tanhf(c[mi][ni][3] + q1) * va1;
        }
        // reduce across the 4 tig lanes (same grp)
        #pragma unroll
        for (int o = 1; o < 4; o <<= 1) {
            rs0 += __shfl_xor_sync(0xffffffffu, rs0, o);
            rs1 += __shfl_xor_sync(0xffffffffu, rs1, o);
        }
        if (tig == 0) {
            int ml = warp_m * 64 + mi * 16 + grp;
            s_red[ml][warp_n] = rs0;
            s_red[ml + 8][warp_n] = rs1;
        }
    }
    __syncthreads();
    if (tid < 128) {
        float e = s_red[tid][0] + s_red[tid][1] + s_red[tid][2] + s_red[tid][3];
        g_et[blockIdx.x * (BSZ * HW) + m0 + tid] = e;
    }
}

// ---------------- K4: softmax over HW per batch ----------------
__global__ void k_softmax(const float* __restrict__ Va_b, float* __restrict__ out_alpha) {
    __shared__ float sx[HW];
    __shared__ float sred[256];
    int b = blockIdx.x;
    int tid = threadIdx.x;
    float vab = Va_b[0];
    float ps = 0.f;
    for (int i = tid; i < HW; i += 256) {
        int m = b * HW + i;
        float e = g_et[m] + g_et[65536 + m] + g_et[131072 + m] + g_et[196608 + m] + vab;
        float ex = expf(e);
        sx[i] = ex;
        ps += ex;
    }
    sred[tid] = ps;
    __syncthreads();
    for (int o = 128; o; o >>= 1) {
        if (tid < o) sred[tid] += sred[tid + o];
        __syncthreads();
    }
    float denom = sred[0] + 1e-8f;
    for (int i = tid; i < HW; i += 256)
        out_alpha[b * HW + i] = sx[i] / denom;
}

// ---------------- K5: context[b][c] = feature[b][c][:] . alpha[b][:] ----------------
__global__ void k_context(const float* __restrict__ feature, const float* __restrict__ alpha) {
    __shared__ float sa[HW];
    int b = blockIdx.y;
    int tid = threadIdx.x;
    for (int i = tid; i < HW; i += 256) sa[i] = alpha[b * HW + i];
    __syncthreads();
    int warp = tid >> 5, lane = tid & 31;
    int c = blockIdx.x * 8 + warp;
    if (c < CH) {
        const float* fr = feature + (b * CH + c) * HW;
        float acc = 0.f;
        for (int i = lane; i < HW; i += 32) acc += fr[i] * sa[i];
        #pragma unroll
        for (int o = 16; o; o >>= 1) acc += __shfl_down_sync(0xffffffffu, acc, o);
        if (lane == 0) g_ctxT[c * 64 + b] = acc;
    }
}

// ---------------- K6: GRU2 -> h2 ----------------
__global__ void k_gru2(const float* __restrict__ wih, const float* __restrict__ whh,
                       const float* __restrict__ bih, const float* __restrict__ bhh,
                       float* __restrict__ out_h2) {
    int b = threadIdx.x;
    int j = blockIdx.x * 8 + threadIdx.y;
    float gi0 = bih[j], gi1 = bih[256 + j], gi2 = bih[512 + j];
    float gh0 = bhh[j], gh1 = bhh[256 + j], gh2 = bhh[512 + j];
    for (int c = 0; c < CH; c++) {
        float cv = g_ctxT[c * 64 + b];
        gi0 += cv * wih[j * CH + c];
        gi1 += cv * wih[(256 + j) * CH + c];
        gi2 += cv * wih[(512 + j) * CH + c];
    }
    for (int k = 0; k < 256; k++) {
        float h = g_predT[k * 64 + b];
        gh0 += h * whh[j * 256 + k];
        gh1 += h * whh[(256 + j) * 256 + k];
        gh2 += h * whh[(512 + j) * 256 + k];
    }
    float r = 1.f / (1.f + expf(-(gi0 + gh0)));
    float z = 1.f / (1.f + expf(-(gi1 + gh1)));
    float n = tanhf(gi2 + r * gh2);
    float hprev = g_predT[j * 64 + b];
    float h2 = (1.f - z) * n + z * hprev;
    out_h2[b * 256 + j] = h2;
    g_h2T[j * 64 + b] = h2;
}

// ---------------- K7: o = embedded + Ws h2 + Wc context ----------------
__global__ void k_ocomp(const float* __restrict__ Ws_w, const float* __restrict__ Ws_b,
                        const float* __restrict__ Wc_w, const float* __restrict__ Wc_b) {
    int b = threadIdx.x;
    int i = blockIdx.x * 8 + threadIdx.y;
    float acc = g_embT[i * 64 + b] + Ws_b[i] + Wc_b[i];
    for (int j = 0; j < 256; j++)
        acc += g_h2T[j * 64 + b] * Ws_w[i * 256 + j];
    for (int c = 0; c < CH; c++)
        acc += g_ctxT[c * 64 + b] * Wc_w[i * CH + c];
    g_oT[i * 64 + b] = acc;
}

// ---------------- K8: maxout pairs + final projection ----------------
__global__ void k_logits(const float* __restrict__ Wo_w, const float* __restrict__ Wo_b,
                         float* __restrict__ out_logits) {
    int b = threadIdx.x;
    int v = blockIdx.x * 8 + threadIdx.y;
    float acc = Wo_b[v];
    for (int i2 = 0; i2 < 128; i2++) {
        float m = fmaxf(g_oT[(2 * i2) * 64 + b], g_oT[(2 * i2 + 1) * 64 + b]);
        acc += m * Wo_w[v * 128 + i2];
    }
    out_logits[b * 128 + v] = acc;
}

// ---------------- launch ----------------
extern "C" void kernel_launch(void* const* d_in, const int* in_sizes, int n_in,
                              void* d_out, int out_size) {
    (void)in_sizes; (void)n_in; (void)out_size;
    const int*   x        = (const int*)  d_in[0];
    const float* hidden   = (const float*)d_in[1];
    const float* feature  = (const float*)d_in[2];
    const float* alpha    = (const float*)d_in[3];
    const float* emb      = (const float*)d_in[4];
    const float* gru1_wih = (const float*)d_in[5];
    const float* gru1_whh = (const float*)d_in[6];
    const float* gru1_bih = (const float*)d_in[7];
    const float* gru1_bhh = (const float*)d_in[8];
    const float* gru2_wih = (const float*)d_in[9];
    const float* gru2_whh = (const float*)d_in[10];
    const float* gru2_bih = (const float*)d_in[11];
    const float* gru2_bhh = (const float*)d_in[12];
    const float* convQ_w  = (const float*)d_in[13];
    const float* convQ_b  = (const float*)d_in[14];
    const float* Wa_w     = (const float*)d_in[15];
    const float* Wa_b     = (const float*)d_in[16];
    const float* Ua_w     = (const float*)d_in[17];
    const float* Ua_b     = (const float*)d_in[18];
    const float* Uf_w     = (const float*)d_in[19];
    const float* Uf_b     = (const float*)d_in[20];
    const float* Va_w     = (const float*)d_in[21];
    const float* Va_b     = (const float*)d_in[22];
    const float* Ws_w     = (const float*)d_in[23];
    const float* Ws_b     = (const float*)d_in[24];
    const float* Wc_w     = (const float*)d_in[25];
    const float* Wc_b     = (const float*)d_in[26];
    const float* Wo_w     = (const float*)d_in[27];
    const float* Wo_b     = (const float*)d_in[28];

    float* out_logits = (float*)d_out;                    // 64*128
    float* out_h2     = out_logits + 64 * 128;            // 64*256
    float* out_alpha  = out_h2 + 64 * 256;                // 64*1024

    k_convT  <<<KCONV, 256>>>(convQ_w);
    k_foldUf <<<(NPP * KCONV * 32 + 255) / 256, 256>>>(Uf_w);
    k_bmatT  <<<(KPAD * NPP + 255) / 256, 256>>>(Ua_w);
    k_misc   <<<(49152 + BSZ * PADW * PADW + 255) / 256, 256>>>(
                 x, hidden, emb, alpha, Uf_w, convQ_b, Ua_b, Uf_b);
    k_gru1   <<<32, dim3(64, 8)>>>(gru1_wih, gru1_whh, gru1_bih, gru1_bhh);
    k_query  <<<64, dim3(64, 8)>>>(Wa_w, Wa_b);
    k_gemm_tc<<<dim3(4, 512), 256>>>(feature, Va_w);
    k_softmax<<<64, 256>>>(Va_b, out_alpha);
    k_context<<<dim3((CH + 7) / 8, 64), 256>>>(feature, out_alpha);
    k_gru2   <<<32, dim3(64, 8)>>>(gru2_wih, gru2_whh, gru2_bih, gru2_bhh, out_h2);
    k_ocomp  <<<32, dim3(64, 8)>>>(Ws_w, Ws_b, Wc_w, Wc_b);
    k_logits <<<16, dim3(64, 8)>>>(Wo_w, Wo_b, out_logits);
}

// round 4
// speedup vs baseline: 4.3121x; 1.2832x over previous
#include <cuda_runtime.h>
#include <cuda_bf16.h>
#include <math.h>
#include <stdint.h>

// ---------------- problem constants ----------------
#define BSZ   64
#define HW    1024        // 32*32
#define CH    684
#define HIDD  256
#define NPP   512
#define KCONV 121         // 11*11
#define KTOT  805         // 684 + 121
#define KPAD  832         // 26 * 32
#define NCHUNK 26         // K chunks of 32
#define PADW  42          // 32 + 2*5

// ---------------- device scratch (no cudaMalloc allowed) ----------------
__device__ __nv_bfloat16 g_Abf[(size_t)BSZ * KPAD * HW];   // [b][k][l] bf16 A (feature + im2col + zero pad)
__device__ __nv_bfloat16 g_BmatTb[KPAD * NPP];             // [k][p] bf16 combined B
__device__ float g_convQT[KCONV * 256];   // [t][q]
__device__ float g_betaPad[BSZ * PADW * PADW];
__device__ float g_embT[HIDD * BSZ];      // [k][b]
__device__ float g_hidT[HIDD * BSZ];      // [k][b]
__device__ float g_predT[HIDD * BSZ];     // [j][b]
__device__ float g_query[BSZ * NPP];      // [b][p], includes Wa_b + D
__device__ float g_D[NPP];                // Ua_b + Uf_b + Uf*convQ_b
__device__ float g_et[4 * BSZ * HW];      // 4 N-block partial slices (deterministic)
__device__ float g_ctxT[CH * BSZ];        // [c][b]
__device__ float g_h2T[HIDD * BSZ];       // [j][b]
__device__ float g_oT[HIDD * BSZ];        // [i][b]

__device__ __forceinline__ uint32_t smem_u32(const void* p) {
    uint32_t a;
    asm("{ .reg .u64 t; cvta.to.shared.u64 t, %1; cvt.u32.u64 %0, t; }" : "=r"(a) : "l"(p));
    return a;
}
// 256B-row swizzle: XOR 16B-granule index with (row % 8)
__device__ __forceinline__ uint32_t swz(uint32_t o) { return o ^ (((o >> 8) & 7u) << 4); }

__device__ __forceinline__ void cp16(uint32_t dst, const void* src) {
    asm volatile("cp.async.cg.shared.global [%0], [%1], 16;" :: "r"(dst), "l"(src) : "memory");
}
__device__ __forceinline__ void cp_commit() { asm volatile("cp.async.commit_group;" ::: "memory"); }

// ---------------- K0a: transpose convQ weights ----------------
__global__ void k_convT(const float* __restrict__ convQ_w) {
    int idx = blockIdx.x * 256 + threadIdx.x;       // idx = t*256 + q
    if (idx >= KCONV * 256) return;
    int q = idx & 255;
    int t = idx >> 8;
    g_convQT[idx] = convQ_w[q * KCONV + t];
}

// ---------------- K0b: fold Uf_w @ convQ_w into BmatTb rows [684..805) ----------------
__global__ void k_foldUf(const float* __restrict__ Uf_w) {
    int w = (blockIdx.x * 256 + threadIdx.x) >> 5;  // global warp id
    int lane = threadIdx.x & 31;
    if (w >= NPP * KCONV) return;
    int t = w % KCONV;
    int p = w / KCONV;
    float acc = 0.f;
    for (int q = lane; q < 256; q += 32)
        acc += Uf_w[p * 256 + q] * g_convQT[t * 256 + q];
    #pragma unroll
    for (int o = 16; o; o >>= 1) acc += __shfl_down_sync(0xffffffffu, acc, o);
    if (lane == 0) g_BmatTb[(CH + t) * NPP + p] = __float2bfloat16(acc);
}

// ---------------- K0c: Ua_w -> BmatTb rows [0..684), zero tail ----------------
__global__ void k_bmatT(const float* __restrict__ Ua_w) {
    int idx = blockIdx.x * 256 + threadIdx.x;   // k*512 + p
    if (idx >= KPAD * NPP) return;
    int k = idx >> 9;
    int p = idx & 511;
    if (k < CH)         g_BmatTb[idx] = __float2bfloat16(Ua_w[p * CH + k]);
    else if (k >= KTOT) g_BmatTb[idx] = __float2bfloat16(0.f);
}

// ---------------- K0d: embT, hidT, D vector (warp-reduce), padded beta ----------------
__global__ void k_misc(const int* __restrict__ x,
                       const float* __restrict__ hidden,
                       const float* __restrict__ emb,
                       const float* __restrict__ alpha,
                       const float* __restrict__ Uf_w,
                       const float* __restrict__ convQ_b,
                       const float* __restrict__ Ua_b,
                       const float* __restrict__ Uf_b) {
    int idx = blockIdx.x * 256 + threadIdx.x;
    if (idx < 16384) {                               // embT[k*64+b] = emb[x[b]][k]
        int k = idx >> 6, b = idx & 63;
        g_embT[idx] = emb[x[b] * 256 + k];
    } else if (idx < 32768) {                        // hidT
        int i = idx - 16384;
        g_hidT[i] = hidden[(i & 63) * 256 + (i >> 6)];
    } else if (idx < 49152) {                        // D[p], one warp per p
        int i = idx - 32768;
        int p = i >> 5, lane = i & 31;
        float acc = 0.f;
        for (int q = lane; q < 256; q += 32)
            acc += Uf_w[p * 256 + q] * convQ_b[q];
        #pragma unroll
        for (int o = 16; o; o >>= 1) acc += __shfl_down_sync(0xffffffffu, acc, o);
        if (lane == 0) g_D[p] = acc + Ua_b[p] + Uf_b[p];
    } else if (idx < 49152 + BSZ * PADW * PADW) {    // betaPad
        int i = idx - 49152;
        int b = i / (PADW * PADW);
        int pos = i % (PADW * PADW);
        int py = pos / PADW, px = pos % PADW;
        int y = py - 5, xx = px - 5;
        float v = 0.f;
        if (y >= 0 && y < 32 && xx >= 0 && xx < 32) v = alpha[b * HW + y * 32 + xx];
        g_betaPad[i] = v;
    }
}

// ---------------- K0e: build bf16 A matrix [b][k][l] ----------------
// blockIdx = b*KPAD + k, thread = l/4 (each thread writes 4 bf16 = 8B)
__global__ void k_prepA(const float* __restrict__ feature) {
    int k = blockIdx.x % KPAD;
    int b = blockIdx.x / KPAD;
    int l = threadIdx.x * 4;
    float v0, v1, v2, v3;
    if (k < CH) {
        float4 f = *(const float4*)&feature[((size_t)(b * CH + k)) * HW + l];
        v0 = f.x; v1 = f.y; v2 = f.z; v3 = f.w;
    } else if (k < KTOT) {
        int t = k - CH;
        int dy = t / 11, dx = t - dy * 11;
        int y = l >> 5, xx = l & 31;   // 4 consecutive l share y (32 | l alignment: l%32 in {0..28})
        const float* bp = g_betaPad + b * (PADW * PADW) + (y + dy) * PADW + dx;
        v0 = bp[xx]; v1 = bp[xx + 1]; v2 = bp[xx + 2]; v3 = bp[xx + 3];
    } else {
        v0 = v1 = v2 = v3 = 0.f;
    }
    __nv_bfloat162 p0 = __nv_bfloat162(__float2bfloat16(v0), __float2bfloat16(v1));
    __nv_bfloat162 p1 = __nv_bfloat162(__float2bfloat16(v2), __float2bfloat16(v3));
    uint2 u = make_uint2(*(uint32_t*)&p0, *(uint32_t*)&p1);
    *(uint2*)&g_Abf[((size_t)(b * KPAD + k)) * HW + l] = u;
}

// ---------------- K1: embed + GRU1 -> predT ----------------
__global__ void k_gru1(const float* __restrict__ wih, const float* __restrict__ whh,
                       const float* __restrict__ bih, const float* __restrict__ bhh) {
    int b = threadIdx.x;
    int j = blockIdx.x * 8 + threadIdx.y;
    float gi0 = bih[j], gi1 = bih[256 + j], gi2 = bih[512 + j];
    float gh0 = bhh[j], gh1 = bhh[256 + j], gh2 = bhh[512 + j];
    for (int k = 0; k < 256; k++) {
        float e = g_embT[k * 64 + b];
        float h = g_hidT[k * 64 + b];
        gi0 += e * wih[j * 256 + k];
        gi1 += e * wih[(256 + j) * 256 + k];
        gi2 += e * wih[(512 + j) * 256 + k];
        gh0 += h * whh[j * 256 + k];
        gh1 += h * whh[(256 + j) * 256 + k];
        gh2 += h * whh[(512 + j) * 256 + k];
    }
    float r = 1.f / (1.f + expf(-(gi0 + gh0)));
    float z = 1.f / (1.f + expf(-(gi1 + gh1)));
    float n = tanhf(gi2 + r * gh2);
    float hprev = g_hidT[j * 64 + b];
    g_predT[j * 64 + b] = (1.f - z) * n + z * hprev;
}

// ---------------- K2: query[b][p] = pred @ Wa^T + Wa_b + D ----------------
__global__ void k_query(const float* __restrict__ Wa_w, const float* __restrict__ Wa_b) {
    int b = threadIdx.x;
    int p = blockIdx.x * 8 + threadIdx.y;
    float acc = Wa_b[p] + g_D[p];
    for (int j = 0; j < 256; j++)
        acc += g_predT[j * 64 + b] * Wa_w[p * 256 + j];
    g_query[b * NPP + p] = acc;
}

// ---------------- K3: fused attention GEMM, bf16 mma + ldmatrix + cp.async ----------------
// grid (4 nblk, 512 mblk), 256 threads = 8 warps (2m x 4n), warp tile 64x32, BK=32, 3 stages.
// SMEM: As[3][32][128] bf16 (8KB/stage), Bs same, both k-major 256B rows, swizzled.
#define TILE_BYTES 8192
#define BS_OFF     (3 * TILE_BYTES)
#define DSMEM_GEMM (6 * TILE_BYTES)

__global__ void __launch_bounds__(256) k_gemm_bf(const float* __restrict__ Va_w) {
    extern __shared__ char dsm[];
    __shared__ float s_red[128][5];
    uint32_t dynb = smem_u32(dsm);

    int tid = threadIdx.x;
    int wid = tid >> 5, lane = tid & 31;
    int grp = lane >> 2, tig = lane & 3;
    int warp_m = wid >> 2, warp_n = wid & 3;     // 2 x 4
    int phase = lane >> 3, lr = lane & 7;

    int n0 = blockIdx.x * 128;
    int m0 = blockIdx.y * 128;
    int b  = m0 >> 10;
    int l0 = m0 & 1023;

    // per-thread cp.async positions (2 granules per tile)
    int r0g = tid >> 4, c0g = tid & 15;          // granule 0: row, col16
    const __nv_bfloat16* gA = g_Abf + (size_t)b * KPAD * HW + l0;
    const __nv_bfloat16* gB = g_BmatTb + n0;
    uint32_t so0 = swz((uint32_t)(r0g * 256 + c0g * 16));
    uint32_t so1 = swz((uint32_t)((r0g + 16) * 256 + c0g * 16));

    // per-thread ldmatrix offsets within a tile
    uint32_t aoff[2][4], boff[2][2];
    #pragma unroll
    for (int ks = 0; ks < 2; ks++) {
        #pragma unroll
        for (int mi = 0; mi < 4; mi++)
            aoff[ks][mi] = swz((uint32_t)((ks * 16 + (phase >> 1) * 8 + lr) * 256 +
                                          (warp_m * 64 + mi * 16 + (phase & 1) * 8) * 2));
        #pragma unroll
        for (int nj = 0; nj < 2; nj++)
            boff[ks][nj] = swz((uint32_t)((ks * 16 + (phase & 1) * 8 + lr) * 256 +
                                          (warp_n * 32 + nj * 16 + (phase >> 1) * 8) * 2));
    }

    float c[4][4][4];
    #pragma unroll
    for (int mi = 0; mi < 4; mi++)
        #pragma unroll
        for (int ni = 0; ni < 4; ni++)
            #pragma unroll
            for (int j = 0; j < 4; j++) c[mi][ni][j] = 0.f;

    #define ISSUE(c_)                                                                 \
    {                                                                                 \
        int k0 = (c_) * 32;                                                           \
        int st = (c_) % 3;                                                            \
        uint32_t ab = dynb + st * TILE_BYTES;                                         \
        uint32_t bb = dynb + BS_OFF + st * TILE_BYTES;                                \
        cp16(ab + so0, gA + (size_t)(k0 + r0g) * HW + c0g * 8);                       \
        cp16(ab + so1, gA + (size_t)(k0 + r0g + 16) * HW + c0g * 8);                  \
        cp16(bb + so0, gB + (k0 + r0g) * NPP + c0g * 8);                              \
        cp16(bb + so1, gB + (k0 + r0g + 16) * NPP + c0g * 8);                         \
        cp_commit();                                                                  \
    }

    ISSUE(0);
    ISSUE(1);

    for (int cc = 0; cc < NCHUNK; cc++) {
        if (cc < NCHUNK - 1) asm volatile("cp.async.wait_group 1;" ::: "memory");
        else                 asm volatile("cp.async.wait_group 0;" ::: "memory");
        __syncthreads();

        int st = cc % 3;
        uint32_t ab = dynb + st * TILE_BYTES;
        uint32_t bb = dynb + BS_OFF + st * TILE_BYTES;

        #pragma unroll
        for (int ks = 0; ks < 2; ks++) {
            uint32_t a[4][4], br[2][4];
            #pragma unroll
            for (int mi = 0; mi < 4; mi++)
                asm volatile("ldmatrix.sync.aligned.m8n8.x4.trans.shared.b16 {%0,%1,%2,%3}, [%4];"
                             : "=r"(a[mi][0]), "=r"(a[mi][1]), "=r"(a[mi][2]), "=r"(a[mi][3])
                             : "r"(ab + aoff[ks][mi]));
            #pragma unroll
            for (int nj = 0; nj < 2; nj++)
                asm volatile("ldmatrix.sync.aligned.m8n8.x4.trans.shared.b16 {%0,%1,%2,%3}, [%4];"
                             : "=r"(br[nj][0]), "=r"(br[nj][1]), "=r"(br[nj][2]), "=r"(br[nj][3])
                             : "r"(bb + boff[ks][nj]));
            #pragma unroll
            for (int mi = 0; mi < 4; mi++)
                #pragma unroll
                for (int nj = 0; nj < 2; nj++)
                    #pragma unroll
                    for (int h = 0; h < 2; h++) {
                        int ni = nj * 2 + h;
                        asm volatile("mma.sync.aligned.m16n8k16.row.col.f32.bf16.bf16.f32 "
                                     "{%0,%1,%2,%3}, {%4,%5,%6,%7}, {%8,%9}, {%0,%1,%2,%3};"
                                     : "+f"(c[mi][ni][0]), "+f"(c[mi][ni][1]),
                                       "+f"(c[mi][ni][2]), "+f"(c[mi][ni][3])
                                     : "r"(a[mi][0]), "r"(a[mi][1]), "r"(a[mi][2]), "r"(a[mi][3]),
                                       "r"(br[nj][h * 2]), "r"(br[nj][h * 2 + 1]));
                    }
        }
        __syncthreads();                 // all warps done reading buf st before it's re-filled
        if (cc + 2 < NCHUNK) ISSUE(cc + 2);
    }

    // ---- epilogue: e[m] = sum_p tanh(C + query[b][p]) * Va[p] ----
    const float* qrow = g_query + b * NPP;
    #pragma unroll
    for (int mi = 0; mi < 4; mi++) {
        float rs0 = 0.f, rs1 = 0.f;
        #pragma unroll
        for (int ni = 0; ni < 4; ni++) {
            int ng = n0 + warp_n * 32 + ni * 8 + 2 * tig;
            float q0 = qrow[ng],     va0 = Va_w[ng];
            float q1 = qrow[ng + 1], va1 = Va_w[ng + 1];
            rs0 += tanhf(c[mi][ni][0] + q0) * va0 + tanhf(c[mi][ni][1] + q1) * va1;
            rs1 += tanhf(c[mi][ni][2] + q0) * va0 + tanhf(c[mi][ni][3] + q1) * va1;
        }
        #pragma unroll
        for (int o = 1; o < 4; o <<= 1) {
            rs0 += __shfl_xor_sync(0xffffffffu, rs0, o);
            rs1 += __shfl_xor_sync(0xffffffffu, rs1, o);
        }
        if (tig == 0) {
            int ml = warp_m * 64 + mi * 16 + grp;
            s_red[ml][warp_n] = rs0;
            s_red[ml + 8][warp_n] = rs1;
        }
    }
    __syncthreads();
    if (tid < 128) {
        float e = s_red[tid][0] + s_red[tid][1] + s_red[tid][2] + s_red[tid][3];
        g_et[blockIdx.x * (BSZ * HW) + m0 + tid] = e;
    }
}

// ---------------- K4: softmax over HW per batch ----------------
__global__ void k_softmax(const float* __restrict__ Va_b, float* __restrict__ out_alpha) {
    __shared__ float sx[HW];
    __shared__ float sred[256];
    int b = blockIdx.x;
    int tid = threadIdx.x;
    float vab = Va_b[0];
    float ps = 0.f;
    for (int i = tid; i < HW; i += 256) {
        int m = b * HW + i;
        float e = g_et[m] + g_et[65536 + m] + g_et[131072 + m] + g_et[196608 + m] + vab;
        float ex = expf(e);
        sx[i] = ex;
        ps += ex;
    }
    sred[tid] = ps;
    __syncthreads();
    for (int o = 128; o; o >>= 1) {
        if (tid < o) sred[tid] += sred[tid + o];
        __syncthreads();
    }
    float denom = sred[0] + 1e-8f;
    for (int i = tid; i < HW; i += 256)
        out_alpha[b * HW + i] = sx[i] / denom;
}

// ---------------- K5: context[b][c] = feature[b][c][:] . alpha[b][:] ----------------
__global__ void k_context(const float* __restrict__ feature, const float* __restrict__ alpha) {
    __shared__ float sa[HW];
    int b = blockIdx.y;
    int tid = threadIdx.x;
    for (int i = tid; i < HW; i += 256) sa[i] = alpha[b * HW + i];
    __syncthreads();
    int warp = tid >> 5, lane = tid & 31;
    int c = blockIdx.x * 8 + warp;
    if (c < CH) {
        const float* fr = feature + (b * CH + c) * HW;
        float acc = 0.f;
        for (int i = lane; i < HW; i += 32) acc += fr[i] * sa[i];
        #pragma unroll
        for (int o = 16; o; o >>= 1) acc += __shfl_down_sync(0xffffffffu, acc, o);
        if (lane == 0) g_ctxT[c * 64 + b] = acc;
    }
}

// ---------------- K6: GRU2 -> h2 ----------------
__global__ void k_gru2(const float* __restrict__ wih, const float* __restrict__ whh,
                       const float* __restrict__ bih, const float* __restrict__ bhh,
                       float* __restrict__ out_h2) {
    int b = threadIdx.x;
    int j = blockIdx.x * 8 + threadIdx.y;
    float gi0 = bih[j], gi1 = bih[256 + j], gi2 = bih[512 + j];
    float gh0 = bhh[j], gh1 = bhh[256 + j], gh2 = bhh[512 + j];
    for (int c = 0; c < CH; c++) {
        float cv = g_ctxT[c * 64 + b];
        gi0 += cv * wih[j * CH + c];
        gi1 += cv * wih[(256 + j) * CH + c];
        gi2 += cv * wih[(512 + j) * CH + c];
    }
    for (int k = 0; k < 256; k++) {
        float h = g_predT[k * 64 + b];
        gh0 += h * whh[j * 256 + k];
        gh1 += h * whh[(256 + j) * 256 + k];
        gh2 += h * whh[(512 + j) * 256 + k];
    }
    float r = 1.f / (1.f + expf(-(gi0 + gh0)));
    float z = 1.f / (1.f + expf(-(gi1 + gh1)));
    float n = tanhf(gi2 + r * gh2);
    float hprev = g_predT[j * 64 + b];
    float h2 = (1.f - z) * n + z * hprev;
    out_h2[b * 256 + j] = h2;
    g_h2T[j * 64 + b] = h2;
}

// ---------------- K7: o = embedded + Ws h2 + Wc context ----------------
__global__ void k_ocomp(const float* __restrict__ Ws_w, const float* __restrict__ Ws_b,
                        const float* __restrict__ Wc_w, const float* __restrict__ Wc_b) {
    int b = threadIdx.x;
    int i = blockIdx.x * 8 + threadIdx.y;
    float acc = g_embT[i * 64 + b] + Ws_b[i] + Wc_b[i];
    for (int j = 0; j < 256; j++)
        acc += g_h2T[j * 64 + b] * Ws_w[i * 256 + j];
    for (int c = 0; c < CH; c++)
        acc += g_ctxT[c * 64 + b] * Wc_w[i * CH + c];
    g_oT[i * 64 + b] = acc;
}

// ---------------- K8: maxout pairs + final projection ----------------
__global__ void k_logits(const float* __restrict__ Wo_w, const float* __restrict__ Wo_b,
                         float* __restrict__ out_logits) {
    int b = threadIdx.x;
    int v = blockIdx.x * 8 + threadIdx.y;
    float acc = Wo_b[v];
    for (int i2 = 0; i2 < 128; i2++) {
        float m = fmaxf(g_oT[(2 * i2) * 64 + b], g_oT[(2 * i2 + 1) * 64 + b]);
        acc += m * Wo_w[v * 128 + i2];
    }
    out_logits[b * 128 + v] = acc;
}

// ---------------- launch ----------------
extern "C" void kernel_launch(void* const* d_in, const int* in_sizes, int n_in,
                              void* d_out, int out_size) {
    (void)in_sizes; (void)n_in; (void)out_size;
    const int*   x        = (const int*)  d_in[0];
    const float* hidden   = (const float*)d_in[1];
    const float* feature  = (const float*)d_in[2];
    const float* alpha    = (const float*)d_in[3];
    const float* emb      = (const float*)d_in[4];
    const float* gru1_wih = (const float*)d_in[5];
    const float* gru1_whh = (const float*)d_in[6];
    const float* gru1_bih = (const float*)d_in[7];
    const float* gru1_bhh = (const float*)d_in[8];
    const float* gru2_wih = (const float*)d_in[9];
    const float* gru2_whh = (const float*)d_in[10];
    const float* gru2_bih = (const float*)d_in[11];
    const float* gru2_bhh = (const float*)d_in[12];
    const float* convQ_w  = (const float*)d_in[13];
    const float* convQ_b  = (const float*)d_in[14];
    const float* Wa_w     = (const float*)d_in[15];
    const float* Wa_b     = (const float*)d_in[16];
    const float* Ua_w     = (const float*)d_in[17];
    const float* Ua_b     = (const float*)d_in[18];
    const float* Uf_w     = (const float*)d_in[19];
    const float* Uf_b     = (const float*)d_in[20];
    const float* Va_w     = (const float*)d_in[21];
    const float* Va_b     = (const float*)d_in[22];
    const float* Ws_w     = (const float*)d_in[23];
    const float* Ws_b     = (const float*)d_in[24];
    const float* Wc_w     = (const float*)d_in[25];
    const float* Wc_b     = (const float*)d_in[26];
    const float* Wo_w     = (const float*)d_in[27];
    const float* Wo_b     = (const float*)d_in[28];

    float* out_logits = (float*)d_out;                    // 64*128
    float* out_h2     = out_logits + 64 * 128;            // 64*256
    float* out_alpha  = out_h2 + 64 * 256;                // 64*1024

    static int s_attr = 0;
    if (!s_attr) {
        cudaFuncSetAttribute(k_gemm_bf, cudaFuncAttributeMaxDynamicSharedMemorySize, DSMEM_GEMM);
        s_attr = 1;
    }

    k_convT  <<<KCONV, 256>>>(convQ_w);
    k_foldUf <<<(NPP * KCONV * 32 + 255) / 256, 256>>>(Uf_w);
    k_bmatT  <<<(KPAD * NPP + 255) / 256, 256>>>(Ua_w);
    k_misc   <<<(49152 + BSZ * PADW * PADW + 255) / 256, 256>>>(
                 x, hidden, emb, alpha, Uf_w, convQ_b, Ua_b, Uf_b);
    k_prepA  <<<BSZ * KPAD, 256>>>(feature);
    k_gru1   <<<32, dim3(64, 8)>>>(gru1_wih, gru1_whh, gru1_bih, gru1_bhh);
    k_query  <<<64, dim3(64, 8)>>>(Wa_w, Wa_b);
    k_gemm_bf<<<dim3(4, 512), 256, DSMEM_GEMM>>>(Va_w);
    k_softmax<<<64, 256>>>(Va_b, out_alpha);
    k_context<<<dim3((CH + 7) / 8, 64), 256>>>(feature, out_alpha);
    k_gru2   <<<32, dim3(64, 8)>>>(gru2_wih, gru2_whh, gru2_bih, gru2_bhh, out_h2);
    k_ocomp  <<<32, dim3(64, 8)>>>(Ws_w, Ws_b, Wc_w, Wc_b);
    k_logits <<<16, dim3(64, 8)>>>(Wo_w, Wo_b, out_logits);
}